// round 1
// baseline (speedup 1.0000x reference)
#include <cuda_runtime.h>

#define NB   2
#define NN   2048
#define MMm  2048
#define DIMD 512
#define HHh  8
#define DHD  64

// Scratch (device globals — no allocation allowed)
__device__ float g_q[(size_t)NB * HHh * NN * DHD];   // [b,h,n,d]
__device__ float g_k[(size_t)NB * HHh * MMm * DHD];  // [b,h,m,d]
__device__ float g_v[(size_t)NB * HHh * NN * DHD];   // [b,h,m,d]
__device__ float g_o[(size_t)NB * NN * DIMD];        // [b,n,inner]

// ---------------------------------------------------------------------------
// Generic 64x64-tile SGEMM, K=512, lda=512. MODE selects epilogue:
//   0: C = x @ W_qv  -> split into g_q / g_v with head-split layout
//   1: C = x1 @ W_k  -> g_k head-split
//   2: C = g_o @ W_out + b_out -> d_out
// ---------------------------------------------------------------------------
template <int MODE>
__global__ void __launch_bounds__(256)
gemm64(const float* __restrict__ A, const float* __restrict__ W, int ncols,
       const float* __restrict__ bias, float* __restrict__ Cout)
{
    __shared__ float As[16][65];  // [k][row] (transposed)
    __shared__ float Ws[16][65];  // [k][col]

    const int tid = threadIdx.x;
    const int tx = tid & 15, ty = tid >> 4;
    const int row0 = blockIdx.y * 64;
    const int col0 = blockIdx.x * 64;
    const float* Ap = (MODE == 2) ? g_o : A;

    float acc[4][4] = {};

    for (int k0 = 0; k0 < 512; k0 += 16) {
        {
            const int r  = tid >> 2;
            const int kq = (tid & 3) * 4;
            float4 v = *reinterpret_cast<const float4*>(
                Ap + (size_t)(row0 + r) * 512 + k0 + kq);
            As[kq + 0][r] = v.x; As[kq + 1][r] = v.y;
            As[kq + 2][r] = v.z; As[kq + 3][r] = v.w;
        }
        {
            const int kk = tid >> 4;
            const int cq = (tid & 15) * 4;
            float4 v = *reinterpret_cast<const float4*>(
                W + (size_t)(k0 + kk) * ncols + col0 + cq);
            Ws[kk][cq + 0] = v.x; Ws[kk][cq + 1] = v.y;
            Ws[kk][cq + 2] = v.z; Ws[kk][cq + 3] = v.w;
        }
        __syncthreads();
#pragma unroll
        for (int kk = 0; kk < 16; kk++) {
            float a[4], b[4];
#pragma unroll
            for (int i = 0; i < 4; i++) a[i] = As[kk][ty * 4 + i];
#pragma unroll
            for (int j = 0; j < 4; j++) b[j] = Ws[kk][tx * 4 + j];
#pragma unroll
            for (int i = 0; i < 4; i++)
#pragma unroll
                for (int j = 0; j < 4; j++)
                    acc[i][j] = fmaf(a[i], b[j], acc[i][j]);
        }
        __syncthreads();
    }

#pragma unroll
    for (int i = 0; i < 4; i++) {
        const int row = row0 + ty * 4 + i;
        const int b = row >> 11;
        const int n = row & 2047;
#pragma unroll
        for (int j = 0; j < 4; j++) {
            const int col = col0 + tx * 4 + j;
            if (MODE == 0) {
                if (col < 512) {
                    const int h = col >> 6, d = col & 63;
                    g_q[((size_t)(b * 8 + h) * 2048 + n) * 64 + d] = acc[i][j];
                } else {
                    const int c2 = col - 512;
                    const int h = c2 >> 6, d = c2 & 63;
                    g_v[((size_t)(b * 8 + h) * 2048 + n) * 64 + d] = acc[i][j];
                }
            } else if (MODE == 1) {
                const int h = col >> 6, d = col & 63;
                g_k[((size_t)(b * 8 + h) * 2048 + n) * 64 + d] = acc[i][j];
            } else {
                Cout[(size_t)row * 512 + col] = acc[i][j] + bias[col];
            }
        }
    }
}

// ---------------------------------------------------------------------------
// Fused attention: per CTA = (b, h, 64-row n-tile). Flash-style loop over m.
// Unnormalized exp (logits bounded ~|6|, fp32-safe), divide by row-sum at end.
// Dynamic smem: Qs[64][65] | KVs[64][65] (K then reused for V) | Ps[64][65]
// (attn_mat tile then reused for P).
// ---------------------------------------------------------------------------
#define SQ 65

__global__ void __launch_bounds__(256)
attn_kernel(const float* __restrict__ amat,
            const float* __restrict__ dots_para,
            const float* __restrict__ mat_para)
{
    extern __shared__ float smbuf[];
    float* Qs  = smbuf;
    float* KVs = smbuf + 64 * SQ;
    float* Ps  = smbuf + 2 * 64 * SQ;

    const int tid = threadIdx.x;
    const int tx = tid & 15, ty = tid >> 4;
    const int b = blockIdx.z, h = blockIdx.y;
    const int n0 = blockIdx.x * 64;

    const float qscale = 0.125f * dots_para[0];  // DH^-0.5 * dots_para
    const float mp = mat_para[0];

    const size_t qbase  = ((size_t)(b * 8 + h) * 2048 + n0) * 64;
    const size_t kvbase = (size_t)(b * 8 + h) * 2048 * 64;
    const size_t abase  = ((size_t)(b * 8 + h) * 2048 + n0) * 2048;

#pragma unroll
    for (int it = 0; it < 4; it++) {
        const int t = tid + it * 256;
        const int r = t >> 4, dq = (t & 15) * 4;
        float4 v = *reinterpret_cast<const float4*>(g_q + qbase + (size_t)r * 64 + dq);
        Qs[r * SQ + dq + 0] = v.x; Qs[r * SQ + dq + 1] = v.y;
        Qs[r * SQ + dq + 2] = v.z; Qs[r * SQ + dq + 3] = v.w;
    }

    float l[4] = {0.f, 0.f, 0.f, 0.f};
    float o[4][4] = {};

    for (int m0 = 0; m0 < 2048; m0 += 64) {
        __syncthreads();  // protect KVs/Ps reuse from prior iteration reads
#pragma unroll
        for (int it = 0; it < 4; it++) {
            const int t = tid + it * 256;
            const int r = t >> 4, dq = (t & 15) * 4;
            float4 v = *reinterpret_cast<const float4*>(
                g_k + kvbase + (size_t)(m0 + r) * 64 + dq);
            KVs[r * SQ + dq + 0] = v.x; KVs[r * SQ + dq + 1] = v.y;
            KVs[r * SQ + dq + 2] = v.z; KVs[r * SQ + dq + 3] = v.w;
        }
        __syncthreads();

        float s[4][4] = {};
#pragma unroll
        for (int d = 0; d < 64; d++) {
            float a[4], bb[4];
#pragma unroll
            for (int i = 0; i < 4; i++) a[i] = Qs[(ty * 4 + i) * SQ + d];
#pragma unroll
            for (int j = 0; j < 4; j++) bb[j] = KVs[(tx * 4 + j) * SQ + d];
#pragma unroll
            for (int i = 0; i < 4; i++)
#pragma unroll
                for (int j = 0; j < 4; j++)
                    s[i][j] = fmaf(a[i], bb[j], s[i][j]);
        }
        __syncthreads();  // done reading K -> reuse KVs for V

        // V tile -> KVs, attn_mat tile -> Ps
#pragma unroll
        for (int it = 0; it < 4; it++) {
            const int t = tid + it * 256;
            const int r = t >> 4, dq = (t & 15) * 4;
            float4 v = *reinterpret_cast<const float4*>(
                g_v + kvbase + (size_t)(m0 + r) * 64 + dq);
            KVs[r * SQ + dq + 0] = v.x; KVs[r * SQ + dq + 1] = v.y;
            KVs[r * SQ + dq + 2] = v.z; KVs[r * SQ + dq + 3] = v.w;
        }
#pragma unroll
        for (int it = 0; it < 4; it++) {
            const int t = tid + it * 256;
            const int r = t >> 4, cq = (t & 15) * 4;
            float4 v = *reinterpret_cast<const float4*>(
                amat + abase + (size_t)r * 2048 + m0 + cq);
            Ps[r * SQ + cq + 0] = v.x; Ps[r * SQ + cq + 1] = v.y;
            Ps[r * SQ + cq + 2] = v.z; Ps[r * SQ + cq + 3] = v.w;
        }
        __syncthreads();

        // logits -> exp -> P (in place: each thread reads/writes its own cells)
#pragma unroll
        for (int i = 0; i < 4; i++)
#pragma unroll
            for (int j = 0; j < 4; j++) {
                const int idx = (ty * 4 + i) * SQ + tx * 4 + j;
                const float p = __expf(s[i][j] * qscale + Ps[idx] * mp);
                l[i] += p;
                Ps[idx] = p;
            }
        __syncthreads();

        // O += P @ V
#pragma unroll
        for (int cc = 0; cc < 64; cc++) {
            float a[4], bb[4];
#pragma unroll
            for (int i = 0; i < 4; i++) a[i] = Ps[(ty * 4 + i) * SQ + cc];
#pragma unroll
            for (int j = 0; j < 4; j++) bb[j] = KVs[cc * SQ + tx * 4 + j];
#pragma unroll
            for (int i = 0; i < 4; i++)
#pragma unroll
                for (int j = 0; j < 4; j++)
                    o[i][j] = fmaf(a[i], bb[j], o[i][j]);
        }
    }

    // reduce row-sums across the 16 tx lanes (xor<=8 stays within 16-lane group)
#pragma unroll
    for (int i = 0; i < 4; i++) {
        float li = l[i];
#pragma unroll
        for (int off = 8; off; off >>= 1)
            li += __shfl_xor_sync(0xffffffffu, li, off);
        const float inv = 1.0f / li;
        const size_t orow = ((size_t)b * 2048 + n0 + ty * 4 + i) * 512 + h * 64;
#pragma unroll
        for (int j = 0; j < 4; j++)
            g_o[orow + tx * 4 + j] = o[i][j] * inv;
    }
}

// ---------------------------------------------------------------------------
extern "C" void kernel_launch(void* const* d_in, const int* in_sizes, int n_in,
                              void* d_out, int out_size)
{
    const float* x    = (const float*)d_in[0];
    const float* x1   = (const float*)d_in[1];
    const float* amat = (const float*)d_in[2];
    const float* dp   = (const float*)d_in[3];
    const float* mp   = (const float*)d_in[4];
    const float* Wqv  = (const float*)d_in[5];
    const float* Wk   = (const float*)d_in[6];
    const float* Wout = (const float*)d_in[7];
    const float* bout = (const float*)d_in[8];
    float* out = (float*)d_out;

    // q,v projection: [4096,512] @ [512,1024]
    gemm64<0><<<dim3(16, 64), 256>>>(x, Wqv, 1024, nullptr, nullptr);
    // k projection: [4096,512] @ [512,512]
    gemm64<1><<<dim3(8, 64), 256>>>(x1, Wk, 512, nullptr, nullptr);

    // fused attention
    const int smem = 3 * 64 * SQ * (int)sizeof(float);  // 49920 B -> opt-in
    cudaFuncSetAttribute(attn_kernel,
                         cudaFuncAttributeMaxDynamicSharedMemorySize, smem);
    attn_kernel<<<dim3(32, 8, 2), 256, smem>>>(amat, dp, mp);

    // output projection + bias: [4096,512] @ [512,512]
    gemm64<2><<<dim3(8, 64), 256>>>(nullptr, Wout, 512, bout, out);
}

// round 2
// speedup vs baseline: 2.1237x; 2.1237x over previous
#include <cuda_runtime.h>
#include <cstdint>

#define NB   2
#define NN   2048
#define DIMD 512
#define HHh  8
#define DHD  64

// Scratch (device globals — no allocation allowed)
__device__ float g_q[(size_t)NB * HHh * NN * DHD];   // [b,h,n,d]
__device__ float g_k[(size_t)NB * HHh * NN * DHD];   // [b,h,m,d]
__device__ float g_v[(size_t)NB * HHh * NN * DHD];   // [b,h,m,d]
__device__ float g_o[(size_t)NB * NN * DIMD];        // [b,n,inner]

__device__ __forceinline__ uint32_t f2tf(float f) {
    uint32_t r;
    asm("cvt.rna.tf32.f32 %0, %1;" : "=r"(r) : "f"(f));
    return r;
}

__device__ __forceinline__ void mma_tf32(float c[4],
                                         uint32_t a0, uint32_t a1, uint32_t a2, uint32_t a3,
                                         uint32_t b0, uint32_t b1) {
    asm volatile(
        "mma.sync.aligned.m16n8k8.row.col.f32.tf32.tf32.f32 "
        "{%0,%1,%2,%3}, {%4,%5,%6,%7}, {%8,%9}, {%0,%1,%2,%3};\n"
        : "+f"(c[0]), "+f"(c[1]), "+f"(c[2]), "+f"(c[3])
        : "r"(a0), "r"(a1), "r"(a2), "r"(a3), "r"(b0), "r"(b1));
}

// ---------------------------------------------------------------------------
// tf32 tensor-core GEMM. CTA tile 128x64, 128 threads (4 warps, each 32 rows
// x 64 cols). K staged in chunks of 32. MODE epilogues as before.
//   As ld=36 (A-frag reads: row varies lane/4 -> ld%32==4 conflict-free)
//   Bs ld=72 (B-frag reads: row varies lane%4 -> ld%32==8 conflict-free)
// ---------------------------------------------------------------------------
template <int MODE>
__global__ void __launch_bounds__(128)
gemm_tc(const float* __restrict__ A, const float* __restrict__ W, int ncols,
        const float* __restrict__ bias, float* __restrict__ Cout)
{
    __shared__ uint32_t As[128][36];
    __shared__ uint32_t Bs[32][72];

    const int tid  = threadIdx.x;
    const int lane = tid & 31;
    const int w    = tid >> 5;
    const int g    = lane >> 2;
    const int tg   = lane & 3;
    const int row0 = blockIdx.y * 128;
    const int col0 = blockIdx.x * 64;
    const float* Ap = (MODE == 2) ? g_o : A;

    float acc[2][8][4] = {};

    for (int k0 = 0; k0 < 512; k0 += 32) {
        // A tile 128x32
#pragma unroll
        for (int i = 0; i < 8; i++) {
            const int r = (tid >> 3) + 16 * i;
            const int c = (tid & 7) * 4;
            float4 v = *reinterpret_cast<const float4*>(
                Ap + (size_t)(row0 + r) * 512 + k0 + c);
            uint4 u = {f2tf(v.x), f2tf(v.y), f2tf(v.z), f2tf(v.w)};
            *reinterpret_cast<uint4*>(&As[r][c]) = u;
        }
        // B tile 32x64
#pragma unroll
        for (int i = 0; i < 4; i++) {
            const int r = (tid >> 4) + 8 * i;
            const int c = (tid & 15) * 4;
            float4 v = *reinterpret_cast<const float4*>(
                W + (size_t)(k0 + r) * ncols + col0 + c);
            uint4 u = {f2tf(v.x), f2tf(v.y), f2tf(v.z), f2tf(v.w)};
            *reinterpret_cast<uint4*>(&Bs[r][c]) = u;
        }
        __syncthreads();

#pragma unroll
        for (int kk = 0; kk < 4; kk++) {
            const int kb = kk * 8;
            uint32_t a[2][4];
#pragma unroll
            for (int mt = 0; mt < 2; mt++) {
                const int r = w * 32 + mt * 16;
                a[mt][0] = As[r + g][kb + tg];
                a[mt][1] = As[r + g + 8][kb + tg];
                a[mt][2] = As[r + g][kb + tg + 4];
                a[mt][3] = As[r + g + 8][kb + tg + 4];
            }
#pragma unroll
            for (int nt = 0; nt < 8; nt++) {
                const uint32_t b0 = Bs[kb + tg][nt * 8 + g];
                const uint32_t b1 = Bs[kb + tg + 4][nt * 8 + g];
                mma_tf32(acc[0][nt], a[0][0], a[0][1], a[0][2], a[0][3], b0, b1);
                mma_tf32(acc[1][nt], a[1][0], a[1][1], a[1][2], a[1][3], b0, b1);
            }
        }
        __syncthreads();
    }

    // Epilogue: C frag c0:(r,2tg) c1:(r,2tg+1) c2:(r+8,2tg) c3:(r+8,2tg+1)
#pragma unroll
    for (int mt = 0; mt < 2; mt++) {
#pragma unroll
        for (int nt = 0; nt < 8; nt++) {
#pragma unroll
            for (int half = 0; half < 2; half++) {
                const int row = row0 + w * 32 + mt * 16 + g + half * 8;
                const int col = col0 + nt * 8 + 2 * tg;
                const float v0 = acc[mt][nt][half * 2 + 0];
                const float v1 = acc[mt][nt][half * 2 + 1];
                const int b = row >> 11, n = row & 2047;
                if (MODE == 0) {
                    float* dst;
                    if (col < 512) {
                        const int h = col >> 6, d = col & 63;
                        dst = &g_q[((size_t)(b * 8 + h) * 2048 + n) * 64 + d];
                    } else {
                        const int c2 = col - 512;
                        const int h = c2 >> 6, d = c2 & 63;
                        dst = &g_v[((size_t)(b * 8 + h) * 2048 + n) * 64 + d];
                    }
                    *reinterpret_cast<float2*>(dst) = make_float2(v0, v1);
                } else if (MODE == 1) {
                    const int h = col >> 6, d = col & 63;
                    float* dst = &g_k[((size_t)(b * 8 + h) * 2048 + n) * 64 + d];
                    *reinterpret_cast<float2*>(dst) = make_float2(v0, v1);
                } else {
                    float* dst = &Cout[(size_t)row * 512 + col];
                    *reinterpret_cast<float2*>(dst) =
                        make_float2(v0 + bias[col], v1 + bias[col + 1]);
                }
            }
        }
    }
}

// ---------------------------------------------------------------------------
// Fused attention, tensor-core version.
// CTA = (b, h, 64-row n-tile), 128 threads (4 warps). Warp w owns S rows
// [w*16, w*16+16), all 64 columns (8 n-tiles of m16n8k8).
// Tiles (uint32 tf32): Qs[64][68], Ks[64][68], Vs[64][72], Ps[64][68].
// attn_mat loaded global->regs at C-frag positions (full 32B sectors).
// ---------------------------------------------------------------------------
#define LDQ 68
#define LDK 68
#define LDV 72
#define LDP 68

__global__ void __launch_bounds__(128)
attn_tc(const float* __restrict__ amat,
        const float* __restrict__ dots_para,
        const float* __restrict__ mat_para)
{
    extern __shared__ uint32_t sm[];
    uint32_t* Qs = sm;                       // 64*68
    uint32_t* Ks = Qs + 64 * LDQ;            // 64*68
    uint32_t* Vs = Ks + 64 * LDK;            // 64*72
    uint32_t* Ps = Vs + 64 * LDV;            // 64*68

    const int tid  = threadIdx.x;
    const int lane = tid & 31;
    const int w    = tid >> 5;
    const int g    = lane >> 2;
    const int tg   = lane & 3;
    const int b  = blockIdx.z, h = blockIdx.y;
    const int n0 = blockIdx.x * 64;

    const float qscale = 0.125f * dots_para[0];
    const float mp = mat_para[0];

    const size_t qbase  = ((size_t)(b * 8 + h) * 2048 + n0) * 64;
    const size_t kvbase = (size_t)(b * 8 + h) * 2048 * 64;
    const size_t abase  = ((size_t)(b * 8 + h) * 2048 + n0) * 2048;

    // Q tile (once)
#pragma unroll
    for (int i = 0; i < 8; i++) {
        const int r = (tid >> 4) + 8 * i;
        const int c = (tid & 15) * 4;
        float4 v = *reinterpret_cast<const float4*>(g_q + qbase + (size_t)r * 64 + c);
        uint4 u = {f2tf(v.x), f2tf(v.y), f2tf(v.z), f2tf(v.w)};
        *reinterpret_cast<uint4*>(&Qs[r * LDQ + c]) = u;
    }

    float O[8][4] = {};
    float rl0 = 0.f, rl1 = 0.f;

    for (int m0 = 0; m0 < 2048; m0 += 64) {
        __syncthreads();  // all warps done with prior Ks/Vs
#pragma unroll
        for (int i = 0; i < 8; i++) {
            const int r = (tid >> 4) + 8 * i;
            const int c = (tid & 15) * 4;
            float4 kv = *reinterpret_cast<const float4*>(
                g_k + kvbase + (size_t)(m0 + r) * 64 + c);
            uint4 uk = {f2tf(kv.x), f2tf(kv.y), f2tf(kv.z), f2tf(kv.w)};
            *reinterpret_cast<uint4*>(&Ks[r * LDK + c]) = uk;
            float4 vv = *reinterpret_cast<const float4*>(
                g_v + kvbase + (size_t)(m0 + r) * 64 + c);
            uint4 uv = {f2tf(vv.x), f2tf(vv.y), f2tf(vv.z), f2tf(vv.w)};
            *reinterpret_cast<uint4*>(&Vs[r * LDV + c]) = uv;
        }
        __syncthreads();

        // S = Q @ K^T   (A = Q rows, B[k=d][n=m] = K[m][d])
        float S[8][4] = {};
#pragma unroll
        for (int kk = 0; kk < 8; kk++) {
            const int kb = kk * 8;
            const int r = w * 16;
            const uint32_t a0 = Qs[(r + g) * LDQ + kb + tg];
            const uint32_t a1 = Qs[(r + g + 8) * LDQ + kb + tg];
            const uint32_t a2 = Qs[(r + g) * LDQ + kb + tg + 4];
            const uint32_t a3 = Qs[(r + g + 8) * LDQ + kb + tg + 4];
#pragma unroll
            for (int nt = 0; nt < 8; nt++) {
                const uint32_t b0 = Ks[(nt * 8 + g) * LDK + kb + tg];
                const uint32_t b1 = Ks[(nt * 8 + g) * LDK + kb + tg + 4];
                mma_tf32(S[nt], a0, a1, a2, a3, b0, b1);
            }
        }

        // bias + exp + row-sum; P -> smem (tf32) for re-fragmentation
        const int rowA = w * 16 + g;
#pragma unroll
        for (int nt = 0; nt < 8; nt++) {
            const size_t acol = abase + m0 + nt * 8 + 2 * tg;
            const float2 amA = *reinterpret_cast<const float2*>(
                amat + acol + (size_t)rowA * 2048);
            const float2 amB = *reinterpret_cast<const float2*>(
                amat + acol + (size_t)(rowA + 8) * 2048);
            const float p0 = __expf(S[nt][0] * qscale + amA.x * mp);
            const float p1 = __expf(S[nt][1] * qscale + amA.y * mp);
            const float p2 = __expf(S[nt][2] * qscale + amB.x * mp);
            const float p3 = __expf(S[nt][3] * qscale + amB.y * mp);
            rl0 += p0 + p1;
            rl1 += p2 + p3;
            uint2 u01 = {f2tf(p0), f2tf(p1)};
            uint2 u23 = {f2tf(p2), f2tf(p3)};
            *reinterpret_cast<uint2*>(&Ps[rowA * LDP + nt * 8 + 2 * tg]) = u01;
            *reinterpret_cast<uint2*>(&Ps[(rowA + 8) * LDP + nt * 8 + 2 * tg]) = u23;
        }
        __syncwarp();  // warp-private rows of Ps: warp-level visibility suffices

        // O += P @ V   (A = P rows, B[k=m][n=d] = V[m][d])
#pragma unroll
        for (int kk = 0; kk < 8; kk++) {
            const int kb = kk * 8;
            const int r = w * 16;
            const uint32_t a0 = Ps[(r + g) * LDP + kb + tg];
            const uint32_t a1 = Ps[(r + g + 8) * LDP + kb + tg];
            const uint32_t a2 = Ps[(r + g) * LDP + kb + tg + 4];
            const uint32_t a3 = Ps[(r + g + 8) * LDP + kb + tg + 4];
#pragma unroll
            for (int nt = 0; nt < 8; nt++) {
                const uint32_t b0 = Vs[(kb + tg) * LDV + nt * 8 + g];
                const uint32_t b1 = Vs[(kb + tg + 4) * LDV + nt * 8 + g];
                mma_tf32(O[nt], a0, a1, a2, a3, b0, b1);
            }
        }
    }

    // row-sum reduce across the quad (tg), normalize, store
#pragma unroll
    for (int off = 1; off <= 2; off <<= 1) {
        rl0 += __shfl_xor_sync(0xffffffffu, rl0, off);
        rl1 += __shfl_xor_sync(0xffffffffu, rl1, off);
    }
    const float inv0 = 1.0f / rl0;
    const float inv1 = 1.0f / rl1;
    const int rowA = n0 + w * 16 + g;
#pragma unroll
    for (int nt = 0; nt < 8; nt++) {
        const int col = h * 64 + nt * 8 + 2 * tg;
        *reinterpret_cast<float2*>(&g_o[((size_t)b * 2048 + rowA) * 512 + col]) =
            make_float2(O[nt][0] * inv0, O[nt][1] * inv0);
        *reinterpret_cast<float2*>(&g_o[((size_t)b * 2048 + rowA + 8) * 512 + col]) =
            make_float2(O[nt][2] * inv1, O[nt][3] * inv1);
    }
}

// ---------------------------------------------------------------------------
extern "C" void kernel_launch(void* const* d_in, const int* in_sizes, int n_in,
                              void* d_out, int out_size)
{
    const float* x    = (const float*)d_in[0];
    const float* x1   = (const float*)d_in[1];
    const float* amat = (const float*)d_in[2];
    const float* dp   = (const float*)d_in[3];
    const float* mp   = (const float*)d_in[4];
    const float* Wqv  = (const float*)d_in[5];
    const float* Wk   = (const float*)d_in[6];
    const float* Wout = (const float*)d_in[7];
    const float* bout = (const float*)d_in[8];
    float* out = (float*)d_out;

    // q,v projection: [4096,512] @ [512,1024]
    gemm_tc<0><<<dim3(16, 32), 128>>>(x, Wqv, 1024, nullptr, nullptr);
    // k projection: [4096,512] @ [512,512]
    gemm_tc<1><<<dim3(8, 32), 128>>>(x1, Wk, 512, nullptr, nullptr);

    // fused attention
    const int smem = (64 * (LDQ + LDK + LDV + LDP)) * (int)sizeof(uint32_t);
    cudaFuncSetAttribute(attn_tc,
                         cudaFuncAttributeMaxDynamicSharedMemorySize, smem);
    attn_tc<<<dim3(32, 8, 2), 128, smem>>>(amat, dp, mp);

    // output projection + bias: [4096,512] @ [512,512]
    gemm_tc<2><<<dim3(8, 32), 128>>>(nullptr, Wout, 512, bout, out);
}

// round 3
// speedup vs baseline: 2.8163x; 1.3261x over previous
#include <cuda_runtime.h>
#include <cstdint>

#define NB   2
#define NN   2048
#define DIMD 512

// Scratch (device globals — no allocation allowed)
__device__ float g_q[(size_t)NB * 8 * NN * 64];   // [b,h,n,d]
__device__ float g_k[(size_t)NB * 8 * NN * 64];   // [b,h,m,d]
__device__ float g_v[(size_t)NB * 8 * NN * 64];   // [b,h,m,d]
__device__ float g_o[(size_t)NB * NN * DIMD];     // [b,n,inner]

__device__ __forceinline__ uint32_t smaddr(const void* p) {
    return (uint32_t)__cvta_generic_to_shared(p);
}
#define CP16(dst_u32, src_ptr) \
    asm volatile("cp.async.cg.shared.global [%0], [%1], 16;\n" \
                 :: "r"(dst_u32), "l"(src_ptr))
#define CPCOMMIT() asm volatile("cp.async.commit_group;\n" ::)
#define CPWAIT0()  asm volatile("cp.async.wait_group 0;\n" ::)

__device__ __forceinline__ void mma_tf32(float c[4],
                                         uint32_t a0, uint32_t a1, uint32_t a2, uint32_t a3,
                                         uint32_t b0, uint32_t b1) {
    asm volatile(
        "mma.sync.aligned.m16n8k8.row.col.f32.tf32.tf32.f32 "
        "{%0,%1,%2,%3}, {%4,%5,%6,%7}, {%8,%9}, {%0,%1,%2,%3};\n"
        : "+f"(c[0]), "+f"(c[1]), "+f"(c[2]), "+f"(c[3])
        : "r"(a0), "r"(a1), "r"(a2), "r"(a3), "r"(b0), "r"(b1));
}

// ---------------------------------------------------------------------------
// tf32 tensor GEMM: CTA tile 128x128, 256 threads (8 warps: 4x2, each 32x64).
// K chunks of 32, 2-stage cp.async double buffer.
// smem stage: As[128][36] | Bs[32][136]  (raw f32 bits, HMMA truncates)
// MODE 0: x@W_qv -> g_q/g_v head-split;  1: x1@W_k -> g_k;  2: g_o@W_out+b.
// ---------------------------------------------------------------------------
#define GA_LD 36
#define GB_LD 136
#define G_STAGE (128 * GA_LD + 32 * GB_LD)   // 8960 words

template <int MODE>
__global__ void __launch_bounds__(256, 2)
gemm_tc(const float* __restrict__ A, const float* __restrict__ W, int ncols,
        const float* __restrict__ bias, float* __restrict__ Cout)
{
    extern __shared__ uint32_t sm[];
    const int tid  = threadIdx.x;
    const int lane = tid & 31;
    const int w    = tid >> 5;
    const int g    = lane >> 2;
    const int tg   = lane & 3;
    const int wr   = w >> 1;     // 0..3
    const int wc   = w & 1;      // 0..1
    const int row0 = blockIdx.y * 128;
    const int col0 = blockIdx.x * 128;
    const float* Ap = (MODE == 2) ? g_o : A;

    uint32_t* const AsS[2] = { sm, sm + G_STAGE };
    uint32_t* const BsS[2] = { sm + 128 * GA_LD, sm + G_STAGE + 128 * GA_LD };

    float acc[2][8][4] = {};

    // prologue: chunk 0
    {
#pragma unroll
        for (int i = 0; i < 4; i++) {
            const int lin = tid + i * 256;
            const int r = lin >> 3, c = (lin & 7) * 4;
            CP16(smaddr(&AsS[0][r * GA_LD + c]), Ap + (size_t)(row0 + r) * 512 + c);
        }
#pragma unroll
        for (int i = 0; i < 4; i++) {
            const int lin = tid + i * 256;
            const int r = lin >> 5, c = (lin & 31) * 4;
            CP16(smaddr(&BsS[0][r * GB_LD + c]), W + (size_t)r * ncols + col0 + c);
        }
        CPCOMMIT();
    }

    for (int ch = 0; ch < 16; ch++) {
        CPWAIT0();
        __syncthreads();
        if (ch < 15) {
            const int k0 = (ch + 1) * 32;
            const int s  = (ch + 1) & 1;
#pragma unroll
            for (int i = 0; i < 4; i++) {
                const int lin = tid + i * 256;
                const int r = lin >> 3, c = (lin & 7) * 4;
                CP16(smaddr(&AsS[s][r * GA_LD + c]),
                     Ap + (size_t)(row0 + r) * 512 + k0 + c);
            }
#pragma unroll
            for (int i = 0; i < 4; i++) {
                const int lin = tid + i * 256;
                const int r = lin >> 5, c = (lin & 31) * 4;
                CP16(smaddr(&BsS[s][r * GB_LD + c]),
                     W + (size_t)(k0 + r) * ncols + col0 + c);
            }
            CPCOMMIT();
        }
        const uint32_t* as = AsS[ch & 1];
        const uint32_t* bs = BsS[ch & 1];
#pragma unroll
        for (int kk = 0; kk < 4; kk++) {
            const int kb = kk * 8;
            uint32_t a[2][4];
#pragma unroll
            for (int mt = 0; mt < 2; mt++) {
                const int r = wr * 32 + mt * 16;
                a[mt][0] = as[(r + g) * GA_LD + kb + tg];
                a[mt][1] = as[(r + g + 8) * GA_LD + kb + tg];
                a[mt][2] = as[(r + g) * GA_LD + kb + tg + 4];
                a[mt][3] = as[(r + g + 8) * GA_LD + kb + tg + 4];
            }
#pragma unroll
            for (int nt = 0; nt < 8; nt++) {
                const int col = wc * 64 + nt * 8 + g;
                const uint32_t b0 = bs[(kb + tg) * GB_LD + col];
                const uint32_t b1 = bs[(kb + tg + 4) * GB_LD + col];
                mma_tf32(acc[0][nt], a[0][0], a[0][1], a[0][2], a[0][3], b0, b1);
                mma_tf32(acc[1][nt], a[1][0], a[1][1], a[1][2], a[1][3], b0, b1);
            }
        }
        // no trailing sync: next write to this stage happens after the NEXT
        // iteration's top __syncthreads(), which all warps reach only after
        // finishing this compute.
    }

    // Epilogue
#pragma unroll
    for (int mt = 0; mt < 2; mt++) {
#pragma unroll
        for (int nt = 0; nt < 8; nt++) {
#pragma unroll
            for (int half = 0; half < 2; half++) {
                const int row = row0 + wr * 32 + mt * 16 + g + half * 8;
                const int col = col0 + wc * 64 + nt * 8 + 2 * tg;
                const float v0 = acc[mt][nt][half * 2 + 0];
                const float v1 = acc[mt][nt][half * 2 + 1];
                const int b = row >> 11, n = row & 2047;
                if (MODE == 0) {
                    float* dst;
                    if (col < 512) {
                        const int h = col >> 6, d = col & 63;
                        dst = &g_q[((size_t)(b * 8 + h) * 2048 + n) * 64 + d];
                    } else {
                        const int c2 = col - 512;
                        const int h = c2 >> 6, d = c2 & 63;
                        dst = &g_v[((size_t)(b * 8 + h) * 2048 + n) * 64 + d];
                    }
                    *reinterpret_cast<float2*>(dst) = make_float2(v0, v1);
                } else if (MODE == 1) {
                    const int h = col >> 6, d = col & 63;
                    float* dst = &g_k[((size_t)(b * 8 + h) * 2048 + n) * 64 + d];
                    *reinterpret_cast<float2*>(dst) = make_float2(v0, v1);
                } else {
                    float* dst = &Cout[(size_t)row * 512 + col];
                    *reinterpret_cast<float2*>(dst) =
                        make_float2(v0 + bias[col], v1 + bias[col + 1]);
                }
            }
        }
    }
}

// ---------------------------------------------------------------------------
// Fused attention, tf32 MMA + cp.async double-buffered K/V.
// CTA = (b, h, 128-row n-tile), 256 threads (8 warps, 16 Q-rows each).
// smem words: Qs[128][68] | Ks[2][64][68] | Vs[2][64][72] | Ps[128][68]
// ---------------------------------------------------------------------------
#define LDQ 68
#define LDK 68
#define LDV 72
#define LDP 68
#define ATT_SMEM_W (128 * LDQ + 2 * 64 * LDK + 2 * 64 * LDV + 128 * LDP)

__global__ void __launch_bounds__(256, 1)
attn_tc(const float* __restrict__ amat,
        const float* __restrict__ dots_para,
        const float* __restrict__ mat_para)
{
    extern __shared__ uint32_t sm[];
    uint32_t* const Qs = sm;                                   // 128*68
    uint32_t* const KsS[2] = { sm + 128 * LDQ,
                               sm + 128 * LDQ + 64 * LDK };
    uint32_t* const VsS[2] = { sm + 128 * LDQ + 2 * 64 * LDK,
                               sm + 128 * LDQ + 2 * 64 * LDK + 64 * LDV };
    uint32_t* const Ps = sm + 128 * LDQ + 2 * 64 * LDK + 2 * 64 * LDV;

    const int tid  = threadIdx.x;
    const int lane = tid & 31;
    const int w    = tid >> 5;
    const int g    = lane >> 2;
    const int tg   = lane & 3;
    const int b  = blockIdx.z, h = blockIdx.y;
    const int n0 = blockIdx.x * 128;

    const float qscale = 0.125f * dots_para[0];
    const float mp = mat_para[0];

    const size_t qbase  = ((size_t)(b * 8 + h) * 2048 + n0) * 64;
    const size_t kvbase = (size_t)(b * 8 + h) * 2048 * 64;
    const size_t abase  = ((size_t)(b * 8 + h) * 2048 + n0) * 2048;

    // Q tile (128x64) + K/V chunk 0 in one async group
#pragma unroll
    for (int i = 0; i < 8; i++) {
        const int lin = tid + i * 256;
        const int r = lin >> 4, c = (lin & 15) * 4;
        CP16(smaddr(&Qs[r * LDQ + c]), g_q + qbase + (size_t)r * 64 + c);
    }
#pragma unroll
    for (int i = 0; i < 4; i++) {
        const int lin = tid + i * 256;
        const int r = lin >> 4, c = (lin & 15) * 4;
        CP16(smaddr(&KsS[0][r * LDK + c]), g_k + kvbase + (size_t)r * 64 + c);
        CP16(smaddr(&VsS[0][r * LDV + c]), g_v + kvbase + (size_t)r * 64 + c);
    }
    CPCOMMIT();

    float O[8][4] = {};
    float rl0 = 0.f, rl1 = 0.f;
    const int rowA = w * 16 + g;

    for (int ch = 0; ch < 32; ch++) {
        CPWAIT0();
        __syncthreads();
        if (ch < 31) {
            const size_t m0 = (size_t)(ch + 1) * 64;
            const int s = (ch + 1) & 1;
#pragma unroll
            for (int i = 0; i < 4; i++) {
                const int lin = tid + i * 256;
                const int r = lin >> 4, c = (lin & 15) * 4;
                CP16(smaddr(&KsS[s][r * LDK + c]),
                     g_k + kvbase + (m0 + r) * 64 + c);
                CP16(smaddr(&VsS[s][r * LDV + c]),
                     g_v + kvbase + (m0 + r) * 64 + c);
            }
            CPCOMMIT();
        }
        const uint32_t* Ks = KsS[ch & 1];
        const uint32_t* Vs = VsS[ch & 1];

        // S = Q @ K^T
        float S[8][4] = {};
#pragma unroll
        for (int kk = 0; kk < 8; kk++) {
            const int kb = kk * 8;
            const int r = w * 16;
            const uint32_t a0 = Qs[(r + g) * LDQ + kb + tg];
            const uint32_t a1 = Qs[(r + g + 8) * LDQ + kb + tg];
            const uint32_t a2 = Qs[(r + g) * LDQ + kb + tg + 4];
            const uint32_t a3 = Qs[(r + g + 8) * LDQ + kb + tg + 4];
#pragma unroll
            for (int nt = 0; nt < 8; nt++) {
                const uint32_t b0 = Ks[(nt * 8 + g) * LDK + kb + tg];
                const uint32_t b1 = Ks[(nt * 8 + g) * LDK + kb + tg + 4];
                mma_tf32(S[nt], a0, a1, a2, a3, b0, b1);
            }
        }

        // bias + exp + row-sum; P (raw f32 bits) -> smem, warp-private rows
        const size_t m0 = (size_t)ch * 64;
#pragma unroll
        for (int nt = 0; nt < 8; nt++) {
            const size_t acol = abase + m0 + nt * 8 + 2 * tg;
            const float2 amA = *reinterpret_cast<const float2*>(
                amat + acol + (size_t)rowA * 2048);
            const float2 amB = *reinterpret_cast<const float2*>(
                amat + acol + (size_t)(rowA + 8) * 2048);
            const float p0 = __expf(S[nt][0] * qscale + amA.x * mp);
            const float p1 = __expf(S[nt][1] * qscale + amA.y * mp);
            const float p2 = __expf(S[nt][2] * qscale + amB.x * mp);
            const float p3 = __expf(S[nt][3] * qscale + amB.y * mp);
            rl0 += p0 + p1;
            rl1 += p2 + p3;
            uint2 u01 = { __float_as_uint(p0), __float_as_uint(p1) };
            uint2 u23 = { __float_as_uint(p2), __float_as_uint(p3) };
            *reinterpret_cast<uint2*>(&Ps[rowA * LDP + nt * 8 + 2 * tg]) = u01;
            *reinterpret_cast<uint2*>(&Ps[(rowA + 8) * LDP + nt * 8 + 2 * tg]) = u23;
        }
        __syncwarp();

        // O += P @ V
#pragma unroll
        for (int kk = 0; kk < 8; kk++) {
            const int kb = kk * 8;
            const int r = w * 16;
            const uint32_t a0 = Ps[(r + g) * LDP + kb + tg];
            const uint32_t a1 = Ps[(r + g + 8) * LDP + kb + tg];
            const uint32_t a2 = Ps[(r + g) * LDP + kb + tg + 4];
            const uint32_t a3 = Ps[(r + g + 8) * LDP + kb + tg + 4];
#pragma unroll
            for (int nt = 0; nt < 8; nt++) {
                const uint32_t b0 = Vs[(kb + tg) * LDV + nt * 8 + g];
                const uint32_t b1 = Vs[(kb + tg + 4) * LDV + nt * 8 + g];
                mma_tf32(O[nt], a0, a1, a2, a3, b0, b1);
            }
        }
    }

    // quad-reduce row sums, normalize, store
#pragma unroll
    for (int off = 1; off <= 2; off <<= 1) {
        rl0 += __shfl_xor_sync(0xffffffffu, rl0, off);
        rl1 += __shfl_xor_sync(0xffffffffu, rl1, off);
    }
    const float inv0 = 1.0f / rl0;
    const float inv1 = 1.0f / rl1;
    const int grow = n0 + rowA;
#pragma unroll
    for (int nt = 0; nt < 8; nt++) {
        const int col = h * 64 + nt * 8 + 2 * tg;
        *reinterpret_cast<float2*>(&g_o[((size_t)b * 2048 + grow) * 512 + col]) =
            make_float2(O[nt][0] * inv0, O[nt][1] * inv0);
        *reinterpret_cast<float2*>(&g_o[((size_t)b * 2048 + grow + 8) * 512 + col]) =
            make_float2(O[nt][2] * inv1, O[nt][3] * inv1);
    }
}

// ---------------------------------------------------------------------------
extern "C" void kernel_launch(void* const* d_in, const int* in_sizes, int n_in,
                              void* d_out, int out_size)
{
    const float* x    = (const float*)d_in[0];
    const float* x1   = (const float*)d_in[1];
    const float* amat = (const float*)d_in[2];
    const float* dp   = (const float*)d_in[3];
    const float* mp   = (const float*)d_in[4];
    const float* Wqv  = (const float*)d_in[5];
    const float* Wk   = (const float*)d_in[6];
    const float* Wout = (const float*)d_in[7];
    const float* bout = (const float*)d_in[8];
    float* out = (float*)d_out;

    const int gsmem = 2 * G_STAGE * (int)sizeof(uint32_t);      // 71680 B
    const int asmem = ATT_SMEM_W * (int)sizeof(uint32_t);       // 141312 B
    cudaFuncSetAttribute(gemm_tc<0>, cudaFuncAttributeMaxDynamicSharedMemorySize, gsmem);
    cudaFuncSetAttribute(gemm_tc<1>, cudaFuncAttributeMaxDynamicSharedMemorySize, gsmem);
    cudaFuncSetAttribute(gemm_tc<2>, cudaFuncAttributeMaxDynamicSharedMemorySize, gsmem);
    cudaFuncSetAttribute(attn_tc, cudaFuncAttributeMaxDynamicSharedMemorySize, asmem);

    // q,v projection: [4096,512] @ [512,1024]
    gemm_tc<0><<<dim3(8, 32), 256, gsmem>>>(x, Wqv, 1024, nullptr, nullptr);
    // k projection: [4096,512] @ [512,512]
    gemm_tc<1><<<dim3(4, 32), 256, gsmem>>>(x1, Wk, 512, nullptr, nullptr);
    // fused attention
    attn_tc<<<dim3(16, 8, 2), 256, asmem>>>(amat, dp, mp);
    // output projection + bias: [4096,512] @ [512,512]
    gemm_tc<2><<<dim3(4, 32), 256, gsmem>>>(nullptr, Wout, 512, bout, out);
}

// round 4
// speedup vs baseline: 2.9674x; 1.0537x over previous
#include <cuda_runtime.h>
#include <cstdint>

#define NB   2
#define NN   2048
#define DIMD 512

// Scratch (device globals — no allocation allowed)
__device__ float g_q[(size_t)NB * 8 * NN * 64];   // [b,h,n,d]
__device__ float g_k[(size_t)NB * 8 * NN * 64];   // [b,h,m,d]
__device__ float g_v[(size_t)NB * 8 * NN * 64];   // [b,h,m,d]
__device__ float g_o[(size_t)NB * NN * DIMD];     // [b,n,inner]

__device__ __forceinline__ uint32_t smaddr(const void* p) {
    return (uint32_t)__cvta_generic_to_shared(p);
}
#define CP16(dst_u32, src_ptr) \
    asm volatile("cp.async.cg.shared.global [%0], [%1], 16;\n" \
                 :: "r"(dst_u32), "l"(src_ptr))
#define CPCOMMIT() asm volatile("cp.async.commit_group;\n" ::)
#define CPWAIT0()  asm volatile("cp.async.wait_group 0;\n" ::)

__device__ __forceinline__ uint32_t f2tf(float f) {
    uint32_t r;
    asm("cvt.rna.tf32.f32 %0, %1;" : "=r"(r) : "f"(f));
    return r;
}
__device__ __forceinline__ float tfr(float f) {      // round-to-nearest tf32 as f32
    return __uint_as_float(f2tf(f));
}
__device__ __forceinline__ float ex2f(float x) {
    float r;
    asm("ex2.approx.ftz.f32 %0, %1;" : "=f"(r) : "f"(x));
    return r;
}

__device__ __forceinline__ void mma_tf32(float c[4],
                                         uint32_t a0, uint32_t a1, uint32_t a2, uint32_t a3,
                                         uint32_t b0, uint32_t b1) {
    asm volatile(
        "mma.sync.aligned.m16n8k8.row.col.f32.tf32.tf32.f32 "
        "{%0,%1,%2,%3}, {%4,%5,%6,%7}, {%8,%9}, {%0,%1,%2,%3};\n"
        : "+f"(c[0]), "+f"(c[1]), "+f"(c[2]), "+f"(c[3])
        : "r"(a0), "r"(a1), "r"(a2), "r"(a3), "r"(b0), "r"(b1));
}

// ---------------------------------------------------------------------------
// tf32 tensor GEMM: CTA tile (64*MT) x 128, 256 threads, 8 warps (4 row x 2
// col), warp tile (16*MT) x 64. K chunks of 32, 2-stage cp.async.
// MODE 0: x@W_qv -> g_q/g_v (rna tf32);  1: x1@W_k -> g_k (rna);
// MODE 2: g_o@W_out + b -> out (full fp32).
// ---------------------------------------------------------------------------
#define GA_LD 36
#define GB_LD 136

template <int MODE, int MT>
__global__ void __launch_bounds__(256, 2)
gemm_tc(const float* __restrict__ A, const float* __restrict__ W, int ncols,
        const float* __restrict__ bias, float* __restrict__ Cout)
{
    constexpr int TM = 64 * MT;
    constexpr int STAGE = TM * GA_LD + 32 * GB_LD;
    extern __shared__ uint32_t sm[];
    const int tid  = threadIdx.x;
    const int lane = tid & 31;
    const int w    = tid >> 5;
    const int g    = lane >> 2;
    const int tg   = lane & 3;
    const int wr   = w >> 1;     // 0..3
    const int wc   = w & 1;      // 0..1
    const int row0 = blockIdx.y * TM;
    const int col0 = blockIdx.x * 128;
    const float* Ap = (MODE == 2) ? g_o : A;

    uint32_t* const AsS[2] = { sm, sm + STAGE };
    uint32_t* const BsS[2] = { sm + TM * GA_LD, sm + STAGE + TM * GA_LD };

    float acc[MT][8][4] = {};

    // prologue: chunk 0
#pragma unroll
    for (int i = 0; i < 2 * MT; i++) {
        const int lin = tid + i * 256;
        const int r = lin >> 3, c = (lin & 7) * 4;
        CP16(smaddr(&AsS[0][r * GA_LD + c]), Ap + (size_t)(row0 + r) * 512 + c);
    }
#pragma unroll
    for (int i = 0; i < 4; i++) {
        const int lin = tid + i * 256;
        const int r = lin >> 5, c = (lin & 31) * 4;
        CP16(smaddr(&BsS[0][r * GB_LD + c]), W + (size_t)r * ncols + col0 + c);
    }
    CPCOMMIT();

    for (int ch = 0; ch < 16; ch++) {
        CPWAIT0();
        __syncthreads();
        if (ch < 15) {
            const int k0 = (ch + 1) * 32;
            const int s  = (ch + 1) & 1;
#pragma unroll
            for (int i = 0; i < 2 * MT; i++) {
                const int lin = tid + i * 256;
                const int r = lin >> 3, c = (lin & 7) * 4;
                CP16(smaddr(&AsS[s][r * GA_LD + c]),
                     Ap + (size_t)(row0 + r) * 512 + k0 + c);
            }
#pragma unroll
            for (int i = 0; i < 4; i++) {
                const int lin = tid + i * 256;
                const int r = lin >> 5, c = (lin & 31) * 4;
                CP16(smaddr(&BsS[s][r * GB_LD + c]),
                     W + (size_t)(k0 + r) * ncols + col0 + c);
            }
            CPCOMMIT();
        }
        const uint32_t* as = AsS[ch & 1];
        const uint32_t* bs = BsS[ch & 1];
#pragma unroll
        for (int kk = 0; kk < 4; kk++) {
            const int kb = kk * 8;
            uint32_t a[MT][4];
#pragma unroll
            for (int mt = 0; mt < MT; mt++) {
                const int r = wr * 16 * MT + mt * 16;
                a[mt][0] = as[(r + g) * GA_LD + kb + tg];
                a[mt][1] = as[(r + g + 8) * GA_LD + kb + tg];
                a[mt][2] = as[(r + g) * GA_LD + kb + tg + 4];
                a[mt][3] = as[(r + g + 8) * GA_LD + kb + tg + 4];
            }
#pragma unroll
            for (int nt = 0; nt < 8; nt++) {
                const int col = wc * 64 + nt * 8 + g;
                const uint32_t b0 = bs[(kb + tg) * GB_LD + col];
                const uint32_t b1 = bs[(kb + tg + 4) * GB_LD + col];
#pragma unroll
                for (int mt = 0; mt < MT; mt++)
                    mma_tf32(acc[mt][nt], a[mt][0], a[mt][1], a[mt][2], a[mt][3], b0, b1);
            }
        }
    }

    // Epilogue
#pragma unroll
    for (int mt = 0; mt < MT; mt++) {
#pragma unroll
        for (int nt = 0; nt < 8; nt++) {
#pragma unroll
            for (int half = 0; half < 2; half++) {
                const int row = row0 + wr * 16 * MT + mt * 16 + g + half * 8;
                const int col = col0 + wc * 64 + nt * 8 + 2 * tg;
                const float v0 = acc[mt][nt][half * 2 + 0];
                const float v1 = acc[mt][nt][half * 2 + 1];
                const int b = row >> 11, n = row & 2047;
                if (MODE == 0) {
                    float* dst;
                    if (col < 512) {
                        const int h = col >> 6, d = col & 63;
                        dst = &g_q[((size_t)(b * 8 + h) * 2048 + n) * 64 + d];
                    } else {
                        const int c2 = col - 512;
                        const int h = c2 >> 6, d = c2 & 63;
                        dst = &g_v[((size_t)(b * 8 + h) * 2048 + n) * 64 + d];
                    }
                    *reinterpret_cast<float2*>(dst) = make_float2(tfr(v0), tfr(v1));
                } else if (MODE == 1) {
                    const int h = col >> 6, d = col & 63;
                    float* dst = &g_k[((size_t)(b * 8 + h) * 2048 + n) * 64 + d];
                    *reinterpret_cast<float2*>(dst) = make_float2(tfr(v0), tfr(v1));
                } else {
                    float* dst = &Cout[(size_t)row * 512 + col];
                    *reinterpret_cast<float2*>(dst) =
                        make_float2(v0 + bias[col], v1 + bias[col + 1]);
                }
            }
        }
    }
}

// ---------------------------------------------------------------------------
// Fused attention, tf32 MMA + cp.async. CTA = (b,h,128-row n-tile), 256 thr
// (8 warps x 16 Q-rows). K/V chunks of 32 rows, 2-stage. 64 chunks.
// smem words: Qs[128][68] | Ks[2][32][68] | Vs[2][32][72] | Ps[128][36]
//   = 8704 + 4352 + 4608 + 4608 = 22272 words = 89088 B  -> occupancy 2.
// ---------------------------------------------------------------------------
#define LDQ 68
#define LDK 68
#define LDV 72
#define LDP 36
#define ATT_SMEM_W (128 * LDQ + 2 * 32 * LDK + 2 * 32 * LDV + 128 * LDP)

__global__ void __launch_bounds__(256, 2)
attn_tc(const float* __restrict__ amat,
        const float* __restrict__ dots_para,
        const float* __restrict__ mat_para)
{
    extern __shared__ uint32_t sm[];
    uint32_t* const Qs = sm;
    uint32_t* const KsS[2] = { sm + 128 * LDQ,
                               sm + 128 * LDQ + 32 * LDK };
    uint32_t* const VsS[2] = { sm + 128 * LDQ + 2 * 32 * LDK,
                               sm + 128 * LDQ + 2 * 32 * LDK + 32 * LDV };
    uint32_t* const Ps = sm + 128 * LDQ + 2 * 32 * LDK + 2 * 32 * LDV;

    const int tid  = threadIdx.x;
    const int lane = tid & 31;
    const int w    = tid >> 5;
    const int g    = lane >> 2;
    const int tg   = lane & 3;
    const int b  = blockIdx.z, h = blockIdx.y;
    const int n0 = blockIdx.x * 128;

    const float qscale = 0.125f * dots_para[0] * 1.44269504f;  // fold log2(e)
    const float mp = mat_para[0] * 1.44269504f;

    const size_t qbase  = ((size_t)(b * 8 + h) * 2048 + n0) * 64;
    const size_t kvbase = (size_t)(b * 8 + h) * 2048 * 64;
    const size_t abase  = ((size_t)(b * 8 + h) * 2048 + n0) * 2048;

    // Q tile (128x64) + K/V chunk 0 in one async group
#pragma unroll
    for (int i = 0; i < 8; i++) {
        const int lin = tid + i * 256;
        const int r = lin >> 4, c = (lin & 15) * 4;
        CP16(smaddr(&Qs[r * LDQ + c]), g_q + qbase + (size_t)r * 64 + c);
    }
#pragma unroll
    for (int i = 0; i < 2; i++) {
        const int lin = tid + i * 256;
        const int r = lin >> 4, c = (lin & 15) * 4;
        CP16(smaddr(&KsS[0][r * LDK + c]), g_k + kvbase + (size_t)r * 64 + c);
        CP16(smaddr(&VsS[0][r * LDV + c]), g_v + kvbase + (size_t)r * 64 + c);
    }
    CPCOMMIT();

    float O[8][4] = {};
    float rl0 = 0.f, rl1 = 0.f;
    const int rowA = w * 16 + g;

    for (int ch = 0; ch < 64; ch++) {
        CPWAIT0();
        __syncthreads();
        if (ch < 63) {
            const size_t m1 = (size_t)(ch + 1) * 32;
            const int s = (ch + 1) & 1;
#pragma unroll
            for (int i = 0; i < 2; i++) {
                const int lin = tid + i * 256;
                const int r = lin >> 4, c = (lin & 15) * 4;
                CP16(smaddr(&KsS[s][r * LDK + c]),
                     g_k + kvbase + (m1 + r) * 64 + c);
                CP16(smaddr(&VsS[s][r * LDV + c]),
                     g_v + kvbase + (m1 + r) * 64 + c);
            }
            CPCOMMIT();
        }
        const uint32_t* Ks = KsS[ch & 1];
        const uint32_t* Vs = VsS[ch & 1];

        // S = Q @ K^T   (32 m-cols)
        float S[4][4] = {};
#pragma unroll
        for (int kk = 0; kk < 8; kk++) {
            const int kb = kk * 8;
            const int r = w * 16;
            const uint32_t a0 = Qs[(r + g) * LDQ + kb + tg];
            const uint32_t a1 = Qs[(r + g + 8) * LDQ + kb + tg];
            const uint32_t a2 = Qs[(r + g) * LDQ + kb + tg + 4];
            const uint32_t a3 = Qs[(r + g + 8) * LDQ + kb + tg + 4];
#pragma unroll
            for (int nt = 0; nt < 4; nt++) {
                const uint32_t b0 = Ks[(nt * 8 + g) * LDK + kb + tg];
                const uint32_t b1 = Ks[(nt * 8 + g) * LDK + kb + tg + 4];
                mma_tf32(S[nt], a0, a1, a2, a3, b0, b1);
            }
        }

        // bias + exp (ex2) + row-sum; P (rna tf32) -> smem, warp-private rows
        const size_t m0 = (size_t)ch * 32;
#pragma unroll
        for (int nt = 0; nt < 4; nt++) {
            const size_t acol = abase + m0 + nt * 8 + 2 * tg;
            const float2 amA = *reinterpret_cast<const float2*>(
                amat + acol + (size_t)rowA * 2048);
            const float2 amB = *reinterpret_cast<const float2*>(
                amat + acol + (size_t)(rowA + 8) * 2048);
            const float p0 = ex2f(S[nt][0] * qscale + amA.x * mp);
            const float p1 = ex2f(S[nt][1] * qscale + amA.y * mp);
            const float p2 = ex2f(S[nt][2] * qscale + amB.x * mp);
            const float p3 = ex2f(S[nt][3] * qscale + amB.y * mp);
            rl0 += p0 + p1;
            rl1 += p2 + p3;
            uint2 u01 = { f2tf(p0), f2tf(p1) };
            uint2 u23 = { f2tf(p2), f2tf(p3) };
            *reinterpret_cast<uint2*>(&Ps[rowA * LDP + nt * 8 + 2 * tg]) = u01;
            *reinterpret_cast<uint2*>(&Ps[(rowA + 8) * LDP + nt * 8 + 2 * tg]) = u23;
        }
        __syncwarp();

        // O += P @ V   (k-range 32)
#pragma unroll
        for (int kk = 0; kk < 4; kk++) {
            const int kb = kk * 8;
            const int r = w * 16;
            const uint32_t a0 = Ps[(r + g) * LDP + kb + tg];
            const uint32_t a1 = Ps[(r + g + 8) * LDP + kb + tg];
            const uint32_t a2 = Ps[(r + g) * LDP + kb + tg + 4];
            const uint32_t a3 = Ps[(r + g + 8) * LDP + kb + tg + 4];
#pragma unroll
            for (int nt = 0; nt < 8; nt++) {
                const uint32_t b0 = Vs[(kb + tg) * LDV + nt * 8 + g];
                const uint32_t b1 = Vs[(kb + tg + 4) * LDV + nt * 8 + g];
                mma_tf32(O[nt], a0, a1, a2, a3, b0, b1);
            }
        }
    }

    // quad-reduce row sums, normalize, store (rna tf32 for final GEMM input)
#pragma unroll
    for (int off = 1; off <= 2; off <<= 1) {
        rl0 += __shfl_xor_sync(0xffffffffu, rl0, off);
        rl1 += __shfl_xor_sync(0xffffffffu, rl1, off);
    }
    const float inv0 = 1.0f / rl0;
    const float inv1 = 1.0f / rl1;
    const int grow = n0 + rowA;
#pragma unroll
    for (int nt = 0; nt < 8; nt++) {
        const int col = h * 64 + nt * 8 + 2 * tg;
        *reinterpret_cast<float2*>(&g_o[((size_t)b * 2048 + grow) * 512 + col]) =
            make_float2(tfr(O[nt][0] * inv0), tfr(O[nt][1] * inv0));
        *reinterpret_cast<float2*>(&g_o[((size_t)b * 2048 + grow + 8) * 512 + col]) =
            make_float2(tfr(O[nt][2] * inv1), tfr(O[nt][3] * inv1));
    }
}

// ---------------------------------------------------------------------------
extern "C" void kernel_launch(void* const* d_in, const int* in_sizes, int n_in,
                              void* d_out, int out_size)
{
    const float* x    = (const float*)d_in[0];
    const float* x1   = (const float*)d_in[1];
    const float* amat = (const float*)d_in[2];
    const float* dp   = (const float*)d_in[3];
    const float* mp   = (const float*)d_in[4];
    const float* Wqv  = (const float*)d_in[5];
    const float* Wk   = (const float*)d_in[6];
    const float* Wout = (const float*)d_in[7];
    const float* bout = (const float*)d_in[8];
    float* out = (float*)d_out;

    const int gsmem2 = 2 * (128 * GA_LD + 32 * GB_LD) * (int)sizeof(uint32_t); // 71680
    const int gsmem1 = 2 * (64 * GA_LD + 32 * GB_LD) * (int)sizeof(uint32_t);  // 53248
    const int asmem  = ATT_SMEM_W * (int)sizeof(uint32_t);                     // 89088
    cudaFuncSetAttribute((const void*)gemm_tc<0, 2>, cudaFuncAttributeMaxDynamicSharedMemorySize, gsmem2);
    cudaFuncSetAttribute((const void*)gemm_tc<1, 1>, cudaFuncAttributeMaxDynamicSharedMemorySize, gsmem1);
    cudaFuncSetAttribute((const void*)gemm_tc<2, 1>, cudaFuncAttributeMaxDynamicSharedMemorySize, gsmem1);
    cudaFuncSetAttribute((const void*)attn_tc, cudaFuncAttributeMaxDynamicSharedMemorySize, asmem);

    // q,v projection: [4096,512] @ [512,1024], 128x128 tiles -> 256 CTAs
    gemm_tc<0, 2><<<dim3(8, 32), 256, gsmem2>>>(x, Wqv, 1024, nullptr, nullptr);
    // k projection: [4096,512] @ [512,512], 64x128 tiles -> 256 CTAs
    gemm_tc<1, 1><<<dim3(4, 64), 256, gsmem1>>>(x1, Wk, 512, nullptr, nullptr);
    // fused attention: 256 CTAs, occupancy 2
    attn_tc<<<dim3(16, 8, 2), 256, asmem>>>(amat, dp, mp);
    // output projection + bias: [4096,512] @ [512,512], 64x128 -> 256 CTAs
    gemm_tc<2, 1><<<dim3(4, 64), 256, gsmem1>>>(nullptr, Wout, 512, bout, out);
}

// round 6
// speedup vs baseline: 5.2402x; 1.7659x over previous
#include <cuda_runtime.h>
#include <cuda_fp16.h>
#include <cstdint>

// -------------------- fp16 scratch (device globals) ------------------------
__device__ __half h_x  [2097152];   // [2,2048,512]
__device__ __half h_x1 [2097152];
__device__ __half h_wqv[524288];    // [512,1024]
__device__ __half h_wk [262144];    // [512,512]
__device__ __half h_wout[262144];   // [512,512]
__device__ __half g_q[2097152];     // [b,h,n,d]
__device__ __half g_k[2097152];     // [b,h,m,d]
__device__ __half g_v[2097152];     // [b,h,m,d]
__device__ __half g_o[2097152];     // [b,n,512]

__device__ __forceinline__ uint32_t smaddr(const void* p) {
    return (uint32_t)__cvta_generic_to_shared(p);
}
#define CP16(dst_u32, src_ptr) \
    asm volatile("cp.async.cg.shared.global [%0], [%1], 16;\n" \
                 :: "r"(dst_u32), "l"(src_ptr))
#define CPCOMMIT() asm volatile("cp.async.commit_group;\n" ::)
#define CPWAIT0()  asm volatile("cp.async.wait_group 0;\n" ::)

__device__ __forceinline__ float ex2f(float x) {
    float r;
    asm("ex2.approx.ftz.f32 %0, %1;" : "=f"(r) : "f"(x));
    return r;
}
__device__ __forceinline__ uint32_t pk(float a, float b) {
    __half2 h = __floats2half2_rn(a, b);
    return *reinterpret_cast<uint32_t*>(&h);
}
__device__ __forceinline__ void mma_h(float c[4],
                                      uint32_t a0, uint32_t a1, uint32_t a2, uint32_t a3,
                                      uint32_t b0, uint32_t b1) {
    asm volatile(
        "mma.sync.aligned.m16n8k16.row.col.f32.f16.f16.f32 "
        "{%0,%1,%2,%3}, {%4,%5,%6,%7}, {%8,%9}, {%0,%1,%2,%3};\n"
        : "+f"(c[0]), "+f"(c[1]), "+f"(c[2]), "+f"(c[3])
        : "r"(a0), "r"(a1), "r"(a2), "r"(a3), "r"(b0), "r"(b1));
}
__device__ __forceinline__ void ldsm4t(uint32_t& r0, uint32_t& r1,
                                       uint32_t& r2, uint32_t& r3, uint32_t addr) {
    asm volatile(
        "ldmatrix.sync.aligned.m8n8.x4.trans.shared.b16 {%0,%1,%2,%3}, [%4];\n"
        : "=r"(r0), "=r"(r1), "=r"(r2), "=r"(r3) : "r"(addr));
}

// -------------------- fp32 -> fp16 conversion ------------------------------
__global__ void __launch_bounds__(256)
convert_k(const float* __restrict__ x, const float* __restrict__ x1,
          const float* __restrict__ wqv, const float* __restrict__ wk,
          const float* __restrict__ wout)
{
    const float* src;
    __half* dst;
    int nq;
    switch (blockIdx.y) {
        case 0: src = x;    dst = h_x;    nq = 524288; break;
        case 1: src = x1;   dst = h_x1;   nq = 524288; break;
        case 2: src = wqv;  dst = h_wqv;  nq = 131072; break;
        case 3: src = wk;   dst = h_wk;   nq = 65536;  break;
        default: src = wout; dst = h_wout; nq = 65536; break;
    }
    const int i = blockIdx.x * 256 + threadIdx.x;
    if (i < nq) {
        float4 v = reinterpret_cast<const float4*>(src)[i];
        uint2 o = { pk(v.x, v.y), pk(v.z, v.w) };
        reinterpret_cast<uint2*>(dst)[i] = o;
    }
}

// ---------------------------------------------------------------------------
// fp16 GEMM: CTA tile 128x128, 256 thr (8 warps 4x2, warp 32x64), K chunks 32,
// 2-stage cp.async. A-frags via contiguous 32-bit LDS (pairs packed), B-frags
// via ldmatrix.x4.trans on row-major [k][n] tile.
//   As u32 pitch 20 (16 data + 4 pad), Bs u32 pitch 68 (64 data + 4 pad)
// MODE 0: h_x@h_wqv -> g_q/g_v;  1: h_x1@h_wk -> g_k;  2: g_o@h_wout+b -> out.
// ---------------------------------------------------------------------------
#define HA_LD 20
#define HB_LD 68
#define H_STAGE (128 * HA_LD + 32 * HB_LD)   // 4736 u32

template <int MODE>
__global__ void __launch_bounds__(256, 2)
gemm_h(int ncols, const float* __restrict__ bias, float* __restrict__ Cout)
{
    extern __shared__ uint32_t sm[];
    const int tid  = threadIdx.x;
    const int lane = tid & 31;
    const int w    = tid >> 5;
    const int g    = lane >> 2;
    const int tg   = lane & 3;
    const int wr   = w >> 1;
    const int wc   = w & 1;
    const int row0 = blockIdx.y * 128;
    const int col0 = blockIdx.x * 128;

    const __half* Ap = (MODE == 0) ? h_x : (MODE == 1) ? h_x1 : g_o;
    const __half* Wp = (MODE == 0) ? h_wqv : (MODE == 1) ? h_wk : h_wout;

    uint32_t* const AsS[2] = { sm, sm + H_STAGE };
    uint32_t* const BsS[2] = { sm + 128 * HA_LD, sm + H_STAGE + 128 * HA_LD };

    float acc[2][8][4] = {};

    // prologue chunk 0
#pragma unroll
    for (int i = 0; i < 2; i++) {
        const int idx = tid + i * 256;
        const int r = idx >> 2, q = idx & 3;
        CP16(smaddr(&AsS[0][r * HA_LD + q * 4]),
             Ap + (size_t)(row0 + r) * 512 + q * 8);
    }
#pragma unroll
    for (int i = 0; i < 2; i++) {
        const int idx = tid + i * 256;
        const int r = idx >> 4, q = idx & 15;
        CP16(smaddr(&BsS[0][r * HB_LD + q * 4]),
             Wp + (size_t)r * ncols + col0 + q * 8);
    }
    CPCOMMIT();

    for (int ch = 0; ch < 16; ch++) {
        CPWAIT0();
        __syncthreads();
        if (ch < 15) {
            const int k0 = (ch + 1) * 32;
            const int s  = (ch + 1) & 1;
#pragma unroll
            for (int i = 0; i < 2; i++) {
                const int idx = tid + i * 256;
                const int r = idx >> 2, q = idx & 3;
                CP16(smaddr(&AsS[s][r * HA_LD + q * 4]),
                     Ap + (size_t)(row0 + r) * 512 + k0 + q * 8);
            }
#pragma unroll
            for (int i = 0; i < 2; i++) {
                const int idx = tid + i * 256;
                const int r = idx >> 4, q = idx & 15;
                CP16(smaddr(&BsS[s][r * HB_LD + q * 4]),
                     Wp + (size_t)(k0 + r) * ncols + col0 + q * 8);
            }
            CPCOMMIT();
        }
        const uint32_t* as = AsS[ch & 1];
        const __half* bsh = reinterpret_cast<const __half*>(BsS[ch & 1]);

#pragma unroll
        for (int kt = 0; kt < 2; kt++) {
            uint32_t a[2][4];
#pragma unroll
            for (int mt = 0; mt < 2; mt++) {
                const int r = wr * 32 + mt * 16;
                a[mt][0] = as[(r + g) * HA_LD + kt * 8 + tg];
                a[mt][1] = as[(r + g + 8) * HA_LD + kt * 8 + tg];
                a[mt][2] = as[(r + g) * HA_LD + kt * 8 + tg + 4];
                a[mt][3] = as[(r + g + 8) * HA_LD + kt * 8 + tg + 4];
            }
            uint32_t bfr[8][2];
#pragma unroll
            for (int ntp = 0; ntp < 4; ntp++) {
                const int kr   = kt * 16 + ((lane >> 3) & 1) * 8 + (lane & 7);
                const int ncol = wc * 64 + (ntp * 2 + (lane >> 4)) * 8;
                ldsm4t(bfr[ntp * 2][0], bfr[ntp * 2][1],
                       bfr[ntp * 2 + 1][0], bfr[ntp * 2 + 1][1],
                       smaddr(&bsh[kr * (HB_LD * 2) + ncol]));
            }
#pragma unroll
            for (int nt = 0; nt < 8; nt++)
#pragma unroll
                for (int mt = 0; mt < 2; mt++)
                    mma_h(acc[mt][nt], a[mt][0], a[mt][1], a[mt][2], a[mt][3],
                          bfr[nt][0], bfr[nt][1]);
        }
    }

    // epilogue
#pragma unroll
    for (int mt = 0; mt < 2; mt++) {
#pragma unroll
        for (int nt = 0; nt < 8; nt++) {
#pragma unroll
            for (int half = 0; half < 2; half++) {
                const int row = row0 + wr * 32 + mt * 16 + g + half * 8;
                const int col = col0 + wc * 64 + nt * 8 + 2 * tg;
                const float v0 = acc[mt][nt][half * 2 + 0];
                const float v1 = acc[mt][nt][half * 2 + 1];
                const int b = row >> 11, n = row & 2047;
                if (MODE == 0) {
                    __half* dst;
                    if (col < 512) {
                        const int h = col >> 6, d = col & 63;
                        dst = &g_q[((size_t)(b * 8 + h) * 2048 + n) * 64 + d];
                    } else {
                        const int c2 = col - 512;
                        const int h = c2 >> 6, d = c2 & 63;
                        dst = &g_v[((size_t)(b * 8 + h) * 2048 + n) * 64 + d];
                    }
                    *reinterpret_cast<uint32_t*>(dst) = pk(v0, v1);
                } else if (MODE == 1) {
                    const int h = col >> 6, d = col & 63;
                    __half* dst = &g_k[((size_t)(b * 8 + h) * 2048 + n) * 64 + d];
                    *reinterpret_cast<uint32_t*>(dst) = pk(v0, v1);
                } else {
                    float* dst = &Cout[(size_t)row * 512 + col];
                    *reinterpret_cast<float2*>(dst) =
                        make_float2(v0 + bias[col], v1 + bias[col + 1]);
                }
            }
        }
    }
}

// ---------------------------------------------------------------------------
// Fused attention, fp16 MMA. CTA = (b,h,128 q-rows), 256 thr (8 warps x 16
// rows). K/V chunks of 32 m-rows, 2-stage cp.async, 64 chunks.
// P stays in registers (FA2 C-frag -> A-frag identity). V B-frags via
// ldmatrix.x4.trans. smem u32: Qs[128][36] | Ks[2][32][36] | Vs[2][32][36]
//   = 9216 u32 = 36,864 B.
// ---------------------------------------------------------------------------
#define AQ_LD 36
#define ATT_SMEM_W (128 * AQ_LD + 4 * 32 * AQ_LD)

__global__ void __launch_bounds__(256, 2)
attn_h(const float* __restrict__ amat,
       const float* __restrict__ dots_para,
       const float* __restrict__ mat_para)
{
    extern __shared__ uint32_t sm[];
    uint32_t* const Qs = sm;
    uint32_t* const KsS[2] = { sm + 128 * AQ_LD, sm + 160 * AQ_LD };
    uint32_t* const VsS[2] = { sm + 192 * AQ_LD, sm + 224 * AQ_LD };

    const int tid  = threadIdx.x;
    const int lane = tid & 31;
    const int w    = tid >> 5;
    const int g    = lane >> 2;
    const int tg   = lane & 3;
    const int b  = blockIdx.z, h = blockIdx.y;
    const int n0 = blockIdx.x * 128;

    const float qscale = 0.125f * dots_para[0] * 1.44269504f;
    const float mp = mat_para[0] * 1.44269504f;

    const size_t qbase  = ((size_t)(b * 8 + h) * 2048 + n0) * 64;
    const size_t kvbase = (size_t)(b * 8 + h) * 2048 * 64;
    const size_t abase  = ((size_t)(b * 8 + h) * 2048 + n0) * 2048;

    // Q (128x64 fp16) + K/V chunk 0
#pragma unroll
    for (int i = 0; i < 4; i++) {
        const int idx = tid + i * 256;
        const int r = idx >> 3, q = idx & 7;
        CP16(smaddr(&Qs[r * AQ_LD + q * 4]), g_q + qbase + (size_t)r * 64 + q * 8);
    }
    {
        const int r = tid >> 3, q = tid & 7;
        CP16(smaddr(&KsS[0][r * AQ_LD + q * 4]), g_k + kvbase + (size_t)r * 64 + q * 8);
        CP16(smaddr(&VsS[0][r * AQ_LD + q * 4]), g_v + kvbase + (size_t)r * 64 + q * 8);
    }
    CPCOMMIT();

    float O[8][4] = {};
    float rl0 = 0.f, rl1 = 0.f;
    const int rowA = w * 16 + g;

    for (int ch = 0; ch < 64; ch++) {
        CPWAIT0();
        __syncthreads();
        if (ch < 63) {
            const size_t m1 = (size_t)(ch + 1) * 32;
            const int s = (ch + 1) & 1;
            const int r = tid >> 3, q = tid & 7;
            CP16(smaddr(&KsS[s][r * AQ_LD + q * 4]),
                 g_k + kvbase + (m1 + r) * 64 + q * 8);
            CP16(smaddr(&VsS[s][r * AQ_LD + q * 4]),
                 g_v + kvbase + (m1 + r) * 64 + q * 8);
            CPCOMMIT();
        }
        const uint32_t* Ks = KsS[ch & 1];
        const __half* Vsh = reinterpret_cast<const __half*>(VsS[ch & 1]);

        // S = Q @ K^T  (128 x 32 per CTA; per warp 16 x 32 = 4 n-tiles)
        float S[4][4] = {};
#pragma unroll
        for (int kt = 0; kt < 4; kt++) {
            const uint32_t a0 = Qs[(rowA) * AQ_LD + kt * 8 + tg];
            const uint32_t a1 = Qs[(rowA + 8) * AQ_LD + kt * 8 + tg];
            const uint32_t a2 = Qs[(rowA) * AQ_LD + kt * 8 + tg + 4];
            const uint32_t a3 = Qs[(rowA + 8) * AQ_LD + kt * 8 + tg + 4];
#pragma unroll
            for (int nt = 0; nt < 4; nt++) {
                const uint32_t b0 = Ks[(nt * 8 + g) * AQ_LD + kt * 8 + tg];
                const uint32_t b1 = Ks[(nt * 8 + g) * AQ_LD + kt * 8 + tg + 4];
                mma_h(S[nt], a0, a1, a2, a3, b0, b1);
            }
        }

        // bias + exp -> P packed directly as PV A-fragments (no smem)
        const size_t m0 = (size_t)ch * 32;
        uint32_t pva[2][4];
#pragma unroll
        for (int nt = 0; nt < 4; nt++) {
            const size_t acol = abase + m0 + nt * 8 + 2 * tg;
            const float2 amA = *reinterpret_cast<const float2*>(
                amat + acol + (size_t)rowA * 2048);
            const float2 amB = *reinterpret_cast<const float2*>(
                amat + acol + (size_t)(rowA + 8) * 2048);
            const float p0 = ex2f(S[nt][0] * qscale + amA.x * mp);
            const float p1 = ex2f(S[nt][1] * qscale + amA.y * mp);
            const float p2 = ex2f(S[nt][2] * qscale + amB.x * mp);
            const float p3 = ex2f(S[nt][3] * qscale + amB.y * mp);
            rl0 += p0 + p1;
            rl1 += p2 + p3;
            pva[nt >> 1][(nt & 1) * 2 + 0] = pk(p0, p1);
            pva[nt >> 1][(nt & 1) * 2 + 1] = pk(p2, p3);
        }

        // O += P @ V  (V B-frags via ldmatrix.trans on row-major [m][d])
#pragma unroll
        for (int j = 0; j < 2; j++) {
            uint32_t vb[8][2];
#pragma unroll
            for (int ntp = 0; ntp < 4; ntp++) {
                const int mr = j * 16 + ((lane >> 3) & 1) * 8 + (lane & 7);
                const int dc = (ntp * 2 + (lane >> 4)) * 8;
                ldsm4t(vb[ntp * 2][0], vb[ntp * 2][1],
                       vb[ntp * 2 + 1][0], vb[ntp * 2 + 1][1],
                       smaddr(&Vsh[mr * (AQ_LD * 2) + dc]));
            }
#pragma unroll
            for (int nt = 0; nt < 8; nt++)
                mma_h(O[nt], pva[j][0], pva[j][1], pva[j][2], pva[j][3],
                      vb[nt][0], vb[nt][1]);
        }
    }

    // quad-reduce row sums, normalize, store fp16
#pragma unroll
    for (int off = 1; off <= 2; off <<= 1) {
        rl0 += __shfl_xor_sync(0xffffffffu, rl0, off);
        rl1 += __shfl_xor_sync(0xffffffffu, rl1, off);
    }
    const float inv0 = 1.0f / rl0;
    const float inv1 = 1.0f / rl1;
    const int grow = n0 + rowA;
#pragma unroll
    for (int nt = 0; nt < 8; nt++) {
        const int col = h * 64 + nt * 8 + 2 * tg;
        *reinterpret_cast<uint32_t*>(&g_o[((size_t)b * 2048 + grow) * 512 + col]) =
            pk(O[nt][0] * inv0, O[nt][1] * inv0);
        *reinterpret_cast<uint32_t*>(&g_o[((size_t)b * 2048 + grow + 8) * 512 + col]) =
            pk(O[nt][2] * inv1, O[nt][3] * inv1);
    }
}

// ---------------------------------------------------------------------------
extern "C" void kernel_launch(void* const* d_in, const int* in_sizes, int n_in,
                              void* d_out, int out_size)
{
    const float* x    = (const float*)d_in[0];
    const float* x1   = (const float*)d_in[1];
    const float* amat = (const float*)d_in[2];
    const float* dp   = (const float*)d_in[3];
    const float* mp   = (const float*)d_in[4];
    const float* Wqv  = (const float*)d_in[5];
    const float* Wk   = (const float*)d_in[6];
    const float* Wout = (const float*)d_in[7];
    const float* bout = (const float*)d_in[8];
    float* out = (float*)d_out;

    const int gsmem = 2 * H_STAGE * (int)sizeof(uint32_t);   // 37,888 B
    const int asmem = ATT_SMEM_W * (int)sizeof(uint32_t);    // 36,864 B

    // fp32 -> fp16 staging
    convert_k<<<dim3(2048, 5), 256>>>(x, x1, Wqv, Wk, Wout);
    // q,v projection: [4096,512] @ [512,1024]
    gemm_h<0><<<dim3(8, 32), 256, gsmem>>>(1024, nullptr, nullptr);
    // k projection: [4096,512] @ [512,512]
    gemm_h<1><<<dim3(4, 32), 256, gsmem>>>(512, nullptr, nullptr);
    // fused attention
    attn_h<<<dim3(16, 8, 2), 256, asmem>>>(amat, dp, mp);
    // output projection + bias
    gemm_h<2><<<dim3(4, 32), 256, gsmem>>>(512, bout, out);
}

// round 7
// speedup vs baseline: 5.8337x; 1.1133x over previous
#include <cuda_runtime.h>
#include <cuda_fp16.h>
#include <cstdint>

// -------------------- fp16 scratch (device globals) ------------------------
__device__ __half h_x  [2097152];   // [2,2048,512]
__device__ __half h_x1 [2097152];
__device__ __half h_wqv[524288];    // [512,1024]
__device__ __half h_wk [262144];    // [512,512]
__device__ __half h_wout[262144];   // [512,512]
__device__ __half g_q[2097152];     // [b,h,n,d]
__device__ __half g_k[2097152];     // [b,h,m,d]
__device__ __half g_v[2097152];     // [b,h,m,d]
__device__ __half g_o[2097152];     // [b,n,512]

__device__ __forceinline__ uint32_t smaddr(const void* p) {
    return (uint32_t)__cvta_generic_to_shared(p);
}
#define CP16(dst_u32, src_ptr) \
    asm volatile("cp.async.cg.shared.global [%0], [%1], 16;\n" \
                 :: "r"(dst_u32), "l"(src_ptr))
#define CPCOMMIT() asm volatile("cp.async.commit_group;\n" ::)
#define CPWAIT0()  asm volatile("cp.async.wait_group 0;\n" ::)

__device__ __forceinline__ float ex2f(float x) {
    float r;
    asm("ex2.approx.ftz.f32 %0, %1;" : "=f"(r) : "f"(x));
    return r;
}
__device__ __forceinline__ uint32_t pk(float a, float b) {
    __half2 h = __floats2half2_rn(a, b);
    return *reinterpret_cast<uint32_t*>(&h);
}
__device__ __forceinline__ void mma_h(float c[4],
                                      uint32_t a0, uint32_t a1, uint32_t a2, uint32_t a3,
                                      uint32_t b0, uint32_t b1) {
    asm volatile(
        "mma.sync.aligned.m16n8k16.row.col.f32.f16.f16.f32 "
        "{%0,%1,%2,%3}, {%4,%5,%6,%7}, {%8,%9}, {%0,%1,%2,%3};\n"
        : "+f"(c[0]), "+f"(c[1]), "+f"(c[2]), "+f"(c[3])
        : "r"(a0), "r"(a1), "r"(a2), "r"(a3), "r"(b0), "r"(b1));
}
__device__ __forceinline__ void ldsm4(uint32_t& r0, uint32_t& r1,
                                      uint32_t& r2, uint32_t& r3, uint32_t addr) {
    asm volatile(
        "ldmatrix.sync.aligned.m8n8.x4.shared.b16 {%0,%1,%2,%3}, [%4];\n"
        : "=r"(r0), "=r"(r1), "=r"(r2), "=r"(r3) : "r"(addr));
}
__device__ __forceinline__ void ldsm4t(uint32_t& r0, uint32_t& r1,
                                       uint32_t& r2, uint32_t& r3, uint32_t addr) {
    asm volatile(
        "ldmatrix.sync.aligned.m8n8.x4.trans.shared.b16 {%0,%1,%2,%3}, [%4];\n"
        : "=r"(r0), "=r"(r1), "=r"(r2), "=r"(r3) : "r"(addr));
}

// -------------------- fp32 -> fp16 conversion ------------------------------
__global__ void __launch_bounds__(256)
convert_k(const float* __restrict__ x, const float* __restrict__ x1,
          const float* __restrict__ wqv, const float* __restrict__ wk,
          const float* __restrict__ wout)
{
    const float* src;
    __half* dst;
    int nq;
    switch (blockIdx.y) {
        case 0: src = x;    dst = h_x;    nq = 524288; break;
        case 1: src = x1;   dst = h_x1;   nq = 524288; break;
        case 2: src = wqv;  dst = h_wqv;  nq = 131072; break;
        case 3: src = wk;   dst = h_wk;   nq = 65536;  break;
        default: src = wout; dst = h_wout; nq = 65536; break;
    }
    const int i = blockIdx.x * 256 + threadIdx.x;
    if (i < nq) {
        float4 v = reinterpret_cast<const float4*>(src)[i];
        uint2 o = { pk(v.x, v.y), pk(v.z, v.w) };
        reinterpret_cast<uint2*>(dst)[i] = o;
    }
}

// ---------------------------------------------------------------------------
// fp16 GEMM: CTA tile 128x128, 256 thr (8 warps 4x2, warp 32x64), K chunks 32,
// 2-stage cp.async. (unchanged from round 6 — proven)
// ---------------------------------------------------------------------------
#define HA_LD 20
#define HB_LD 68
#define H_STAGE (128 * HA_LD + 32 * HB_LD)   // 4736 u32

template <int MODE>
__global__ void __launch_bounds__(256, 2)
gemm_h(int ncols, const float* __restrict__ bias, float* __restrict__ Cout)
{
    extern __shared__ uint32_t sm[];
    const int tid  = threadIdx.x;
    const int lane = tid & 31;
    const int w    = tid >> 5;
    const int g    = lane >> 2;
    const int tg   = lane & 3;
    const int wr   = w >> 1;
    const int wc   = w & 1;
    const int row0 = blockIdx.y * 128;
    const int col0 = blockIdx.x * 128;

    const __half* Ap = (MODE == 0) ? h_x : (MODE == 1) ? h_x1 : g_o;
    const __half* Wp = (MODE == 0) ? h_wqv : (MODE == 1) ? h_wk : h_wout;

    uint32_t* const AsS[2] = { sm, sm + H_STAGE };
    uint32_t* const BsS[2] = { sm + 128 * HA_LD, sm + H_STAGE + 128 * HA_LD };

    float acc[2][8][4] = {};

#pragma unroll
    for (int i = 0; i < 2; i++) {
        const int idx = tid + i * 256;
        const int r = idx >> 2, q = idx & 3;
        CP16(smaddr(&AsS[0][r * HA_LD + q * 4]),
             Ap + (size_t)(row0 + r) * 512 + q * 8);
    }
#pragma unroll
    for (int i = 0; i < 2; i++) {
        const int idx = tid + i * 256;
        const int r = idx >> 4, q = idx & 15;
        CP16(smaddr(&BsS[0][r * HB_LD + q * 4]),
             Wp + (size_t)r * ncols + col0 + q * 8);
    }
    CPCOMMIT();

    for (int ch = 0; ch < 16; ch++) {
        CPWAIT0();
        __syncthreads();
        if (ch < 15) {
            const int k0 = (ch + 1) * 32;
            const int s  = (ch + 1) & 1;
#pragma unroll
            for (int i = 0; i < 2; i++) {
                const int idx = tid + i * 256;
                const int r = idx >> 2, q = idx & 3;
                CP16(smaddr(&AsS[s][r * HA_LD + q * 4]),
                     Ap + (size_t)(row0 + r) * 512 + k0 + q * 8);
            }
#pragma unroll
            for (int i = 0; i < 2; i++) {
                const int idx = tid + i * 256;
                const int r = idx >> 4, q = idx & 15;
                CP16(smaddr(&BsS[s][r * HB_LD + q * 4]),
                     Wp + (size_t)(k0 + r) * ncols + col0 + q * 8);
            }
            CPCOMMIT();
        }
        const uint32_t* as = AsS[ch & 1];
        const __half* bsh = reinterpret_cast<const __half*>(BsS[ch & 1]);

#pragma unroll
        for (int kt = 0; kt < 2; kt++) {
            uint32_t a[2][4];
#pragma unroll
            for (int mt = 0; mt < 2; mt++) {
                const int r = wr * 32 + mt * 16;
                a[mt][0] = as[(r + g) * HA_LD + kt * 8 + tg];
                a[mt][1] = as[(r + g + 8) * HA_LD + kt * 8 + tg];
                a[mt][2] = as[(r + g) * HA_LD + kt * 8 + tg + 4];
                a[mt][3] = as[(r + g + 8) * HA_LD + kt * 8 + tg + 4];
            }
            uint32_t bfr[8][2];
#pragma unroll
            for (int ntp = 0; ntp < 4; ntp++) {
                const int kr   = kt * 16 + ((lane >> 3) & 1) * 8 + (lane & 7);
                const int ncol = wc * 64 + (ntp * 2 + (lane >> 4)) * 8;
                ldsm4t(bfr[ntp * 2][0], bfr[ntp * 2][1],
                       bfr[ntp * 2 + 1][0], bfr[ntp * 2 + 1][1],
                       smaddr(&bsh[kr * (HB_LD * 2) + ncol]));
            }
#pragma unroll
            for (int nt = 0; nt < 8; nt++)
#pragma unroll
                for (int mt = 0; mt < 2; mt++)
                    mma_h(acc[mt][nt], a[mt][0], a[mt][1], a[mt][2], a[mt][3],
                          bfr[nt][0], bfr[nt][1]);
        }
    }

#pragma unroll
    for (int mt = 0; mt < 2; mt++) {
#pragma unroll
        for (int nt = 0; nt < 8; nt++) {
#pragma unroll
            for (int half = 0; half < 2; half++) {
                const int row = row0 + wr * 32 + mt * 16 + g + half * 8;
                const int col = col0 + wc * 64 + nt * 8 + 2 * tg;
                const float v0 = acc[mt][nt][half * 2 + 0];
                const float v1 = acc[mt][nt][half * 2 + 1];
                const int b = row >> 11, n = row & 2047;
                if (MODE == 0) {
                    __half* dst;
                    if (col < 512) {
                        const int h = col >> 6, d = col & 63;
                        dst = &g_q[((size_t)(b * 8 + h) * 2048 + n) * 64 + d];
                    } else {
                        const int c2 = col - 512;
                        const int h = c2 >> 6, d = c2 & 63;
                        dst = &g_v[((size_t)(b * 8 + h) * 2048 + n) * 64 + d];
                    }
                    *reinterpret_cast<uint32_t*>(dst) = pk(v0, v1);
                } else if (MODE == 1) {
                    const int h = col >> 6, d = col & 63;
                    __half* dst = &g_k[((size_t)(b * 8 + h) * 2048 + n) * 64 + d];
                    *reinterpret_cast<uint32_t*>(dst) = pk(v0, v1);
                } else {
                    float* dst = &Cout[(size_t)row * 512 + col];
                    *reinterpret_cast<float2*>(dst) =
                        make_float2(v0 + bias[col], v1 + bias[col + 1]);
                }
            }
        }
    }
}

// ---------------------------------------------------------------------------
// Fused attention, fp16 MMA. CTA = (b,h,128 q-rows), 256 thr (8 warps x 16
// rows). K/V chunks of 32 m-rows + attn_mat chunk tile (128x32 f32), all
// 2-stage cp.async double-buffered. QK frags via ldmatrix.x4 (Q non-trans,
// K non-trans packing 2 n-tiles x k16). P stays in registers. V via
// ldmatrix.x4.trans.
// smem u32: Qs[128][36] | Ks[2][32][36] | Vs[2][32][36] | Am[2][128][36]
//   = 4608 + 2304 + 2304 + 9216 = 18432 u32 = 73,728 B -> occupancy 2.
// ---------------------------------------------------------------------------
#define AQ_LD 36
#define ATT_SMEM_W (128 * AQ_LD + 4 * 32 * AQ_LD + 2 * 128 * AQ_LD)

__global__ void __launch_bounds__(256, 2)
attn_h(const float* __restrict__ amat,
       const float* __restrict__ dots_para,
       const float* __restrict__ mat_para)
{
    extern __shared__ uint32_t sm[];
    uint32_t* const Qs = sm;                              // 128*36
    uint32_t* const KsS[2] = { sm + 128 * AQ_LD, sm + 160 * AQ_LD };
    uint32_t* const VsS[2] = { sm + 192 * AQ_LD, sm + 224 * AQ_LD };
    uint32_t* const AmS[2] = { sm + 256 * AQ_LD, sm + 384 * AQ_LD };

    const int tid  = threadIdx.x;
    const int lane = tid & 31;
    const int w    = tid >> 5;
    const int g    = lane >> 2;
    const int tg   = lane & 3;
    const int b  = blockIdx.z, h = blockIdx.y;
    const int n0 = blockIdx.x * 128;

    const float qscale = 0.125f * dots_para[0] * 1.44269504f;
    const float mp = mat_para[0] * 1.44269504f;

    const size_t qbase  = ((size_t)(b * 8 + h) * 2048 + n0) * 64;
    const size_t kvbase = (size_t)(b * 8 + h) * 2048 * 64;
    const size_t abase  = ((size_t)(b * 8 + h) * 2048 + n0) * 2048;

    // Q (128x64 fp16) + K/V chunk 0 + amat chunk 0
#pragma unroll
    for (int i = 0; i < 4; i++) {
        const int idx = tid + i * 256;
        const int r = idx >> 3, q = idx & 7;
        CP16(smaddr(&Qs[r * AQ_LD + q * 4]), g_q + qbase + (size_t)r * 64 + q * 8);
    }
    {
        const int r = tid >> 3, q = tid & 7;
        CP16(smaddr(&KsS[0][r * AQ_LD + q * 4]), g_k + kvbase + (size_t)r * 64 + q * 8);
        CP16(smaddr(&VsS[0][r * AQ_LD + q * 4]), g_v + kvbase + (size_t)r * 64 + q * 8);
    }
#pragma unroll
    for (int i = 0; i < 4; i++) {
        const int idx = tid + i * 256;
        const int r = idx >> 3, c = (idx & 7) * 4;
        CP16(smaddr(&AmS[0][r * AQ_LD + c]), amat + abase + (size_t)r * 2048 + c);
    }
    CPCOMMIT();

    float O[8][4] = {};
    float rl0 = 0.f, rl1 = 0.f;
    const int rowA = w * 16 + g;

    for (int ch = 0; ch < 64; ch++) {
        CPWAIT0();
        __syncthreads();
        if (ch < 63) {
            const size_t m1 = (size_t)(ch + 1) * 32;
            const int s = (ch + 1) & 1;
            {
                const int r = tid >> 3, q = tid & 7;
                CP16(smaddr(&KsS[s][r * AQ_LD + q * 4]),
                     g_k + kvbase + (m1 + r) * 64 + q * 8);
                CP16(smaddr(&VsS[s][r * AQ_LD + q * 4]),
                     g_v + kvbase + (m1 + r) * 64 + q * 8);
            }
#pragma unroll
            for (int i = 0; i < 4; i++) {
                const int idx = tid + i * 256;
                const int r = idx >> 3, c = (idx & 7) * 4;
                CP16(smaddr(&AmS[s][r * AQ_LD + c]),
                     amat + abase + (size_t)r * 2048 + m1 + c);
            }
            CPCOMMIT();
        }
        const __half* Qsh = reinterpret_cast<const __half*>(Qs);
        const __half* Ksh = reinterpret_cast<const __half*>(KsS[ch & 1]);
        const __half* Vsh = reinterpret_cast<const __half*>(VsS[ch & 1]);
        const float*  Am  = reinterpret_cast<const float*>(AmS[ch & 1]);

        // S = Q @ K^T  (per warp 16 x 32), all frags via ldmatrix.x4
        float S[4][4] = {};
#pragma unroll
        for (int kt = 0; kt < 4; kt++) {
            uint32_t aq0, aq1, aq2, aq3;
            {
                const int mr = w * 16 + (lane & 15);
                const int kc = kt * 16 + (lane >> 4) * 8;
                ldsm4(aq0, aq1, aq2, aq3, smaddr(&Qsh[mr * (AQ_LD * 2) + kc]));
            }
#pragma unroll
            for (int ntp = 0; ntp < 2; ntp++) {
                uint32_t kb0, kb1, kb2, kb3;
                const int nr = ntp * 16 + ((lane >> 4) & 1) * 8 + (lane & 7);
                const int kc = kt * 16 + ((lane >> 3) & 1) * 8;
                ldsm4(kb0, kb1, kb2, kb3, smaddr(&Ksh[nr * (AQ_LD * 2) + kc]));
                mma_h(S[ntp * 2],     aq0, aq1, aq2, aq3, kb0, kb1);
                mma_h(S[ntp * 2 + 1], aq0, aq1, aq2, aq3, kb2, kb3);
            }
        }

        // bias (from smem-staged amat) + exp -> P packed as PV A-fragments
        uint32_t pva[2][4];
#pragma unroll
        for (int nt = 0; nt < 4; nt++) {
            const int acol = nt * 8 + 2 * tg;
            const float2 amA = *reinterpret_cast<const float2*>(
                &Am[rowA * AQ_LD + acol]);
            const float2 amB = *reinterpret_cast<const float2*>(
                &Am[(rowA + 8) * AQ_LD + acol]);
            const float p0 = ex2f(S[nt][0] * qscale + amA.x * mp);
            const float p1 = ex2f(S[nt][1] * qscale + amA.y * mp);
            const float p2 = ex2f(S[nt][2] * qscale + amB.x * mp);
            const float p3 = ex2f(S[nt][3] * qscale + amB.y * mp);
            rl0 += p0 + p1;
            rl1 += p2 + p3;
            pva[nt >> 1][(nt & 1) * 2 + 0] = pk(p0, p1);
            pva[nt >> 1][(nt & 1) * 2 + 1] = pk(p2, p3);
        }

        // O += P @ V  (V B-frags via ldmatrix.trans on row-major [m][d])
#pragma unroll
        for (int j = 0; j < 2; j++) {
            uint32_t vb[8][2];
#pragma unroll
            for (int ntp = 0; ntp < 4; ntp++) {
                const int mr = j * 16 + ((lane >> 3) & 1) * 8 + (lane & 7);
                const int dc = (ntp * 2 + (lane >> 4)) * 8;
                ldsm4t(vb[ntp * 2][0], vb[ntp * 2][1],
                       vb[ntp * 2 + 1][0], vb[ntp * 2 + 1][1],
                       smaddr(&Vsh[mr * (AQ_LD * 2) + dc]));
            }
#pragma unroll
            for (int nt = 0; nt < 8; nt++)
                mma_h(O[nt], pva[j][0], pva[j][1], pva[j][2], pva[j][3],
                      vb[nt][0], vb[nt][1]);
        }
    }

    // quad-reduce row sums, normalize, store fp16
#pragma unroll
    for (int off = 1; off <= 2; off <<= 1) {
        rl0 += __shfl_xor_sync(0xffffffffu, rl0, off);
        rl1 += __shfl_xor_sync(0xffffffffu, rl1, off);
    }
    const float inv0 = 1.0f / rl0;
    const float inv1 = 1.0f / rl1;
    const int grow = n0 + rowA;
#pragma unroll
    for (int nt = 0; nt < 8; nt++) {
        const int col = h * 64 + nt * 8 + 2 * tg;
        *reinterpret_cast<uint32_t*>(&g_o[((size_t)b * 2048 + grow) * 512 + col]) =
            pk(O[nt][0] * inv0, O[nt][1] * inv0);
        *reinterpret_cast<uint32_t*>(&g_o[((size_t)b * 2048 + grow + 8) * 512 + col]) =
            pk(O[nt][2] * inv1, O[nt][3] * inv1);
    }
}

// ---------------------------------------------------------------------------
extern "C" void kernel_launch(void* const* d_in, const int* in_sizes, int n_in,
                              void* d_out, int out_size)
{
    const float* x    = (const float*)d_in[0];
    const float* x1   = (const float*)d_in[1];
    const float* amat = (const float*)d_in[2];
    const float* dp   = (const float*)d_in[3];
    const float* mp   = (const float*)d_in[4];
    const float* Wqv  = (const float*)d_in[5];
    const float* Wk   = (const float*)d_in[6];
    const float* Wout = (const float*)d_in[7];
    const float* bout = (const float*)d_in[8];
    float* out = (float*)d_out;

    const int gsmem = 2 * H_STAGE * (int)sizeof(uint32_t);   // 37,888 B
    const int asmem = ATT_SMEM_W * (int)sizeof(uint32_t);    // 73,728 B
    cudaFuncSetAttribute((const void*)attn_h,
                         cudaFuncAttributeMaxDynamicSharedMemorySize, asmem);

    // fp32 -> fp16 staging
    convert_k<<<dim3(2048, 5), 256>>>(x, x1, Wqv, Wk, Wout);
    // q,v projection: [4096,512] @ [512,1024]
    gemm_h<0><<<dim3(8, 32), 256, gsmem>>>(1024, nullptr, nullptr);
    // k projection: [4096,512] @ [512,512]
    gemm_h<1><<<dim3(4, 32), 256, gsmem>>>(512, nullptr, nullptr);
    // fused attention
    attn_h<<<dim3(16, 8, 2), 256, asmem>>>(amat, dp, mp);
    // output projection + bias
    gemm_h<2><<<dim3(4, 32), 256, gsmem>>>(512, bout, out);
}